// round 1
// baseline (speedup 1.0000x reference)
#include <cuda_runtime.h>
#include <math.h>

#define N 8192
#define T 32
#define NB (N / T)              // 256 tile-blocks per dim
#define NPAIRS (NB * (NB + 1) / 2)

__device__ float g_rowsum[N];
__device__ float g_dinv[N];

__device__ __forceinline__ int pair_offset(int bi) {
    // number of (bi',bj') pairs with bi' < bi  (bj >= bi)
    return bi * NB - (bi * (bi - 1)) / 2;
}

__device__ __forceinline__ void decode_pair(int p, int& bi, int& bj) {
    // solve p = bi*NB - bi(bi-1)/2 + (bj-bi)
    float disc = (float)((2 * NB + 1) * (2 * NB + 1) - 8 * p);
    int b = (int)(((float)(2 * NB + 1) - sqrtf(disc)) * 0.5f);
    if (b < 0) b = 0;
    if (b > NB - 1) b = NB - 1;
    while (b + 1 <= NB - 1 && pair_offset(b + 1) <= p) b++;
    while (b > 0 && pair_offset(b) > p) b--;
    bi = b;
    bj = bi + (p - pair_offset(b));
}

__global__ void zero_rowsum_kernel() {
    int i = blockIdx.x * blockDim.x + threadIdx.x;
    if (i < N) g_rowsum[i] = 0.0f;
}

// Pass 1: rowsum[i] = sum_j ( max(adj[i,j], adj[j,i]) + (i==j) )
// One block per upper-triangular tile pair (bi <= bj). Each adj element read once.
__global__ __launch_bounds__(256) void pass1_kernel(const float* __restrict__ adj) {
    int bi, bj;
    decode_pair(blockIdx.x, bi, bj);
    const int r0 = bi * T;
    const int c0 = bj * T;
    const int tx = threadIdx.x;   // 0..31
    const int ty = threadIdx.y;   // 0..7

    __shared__ float Bs[T][T + 1];
    __shared__ float Cs[8][T + 1];

    // Load B tile = adj[c0.., r0..] (the transpose partner), coalesced.
    #pragma unroll
    for (int k = 0; k < 4; k++) {
        int ry = ty + k * 8;
        Bs[ry][tx] = adj[(size_t)(c0 + ry) * N + (r0 + tx)];
    }
    __syncthreads();

    float cacc = 0.0f;   // column partial (this thread's tx column, its 4 rows)
    #pragma unroll
    for (int k = 0; k < 4; k++) {
        int r = ty + k * 8;
        float a = adj[(size_t)(r0 + r) * N + (c0 + tx)];
        float m = fmaxf(a, Bs[tx][r]);               // Bs[tx][r] = adj[c0+tx][r0+r]? no: adj[(c0+tx? )]
        if (bi == bj && r == tx) m += 1.0f;          // self-loop on diagonal
        // row-sum reduce across the warp (tx = lane)
        float s = m;
        #pragma unroll
        for (int o = 16; o > 0; o >>= 1) s += __shfl_down_sync(0xffffffffu, s, o);
        if (tx == 0) atomicAdd(&g_rowsum[r0 + r], s);
        cacc += m;
    }

    if (bi != bj) {
        // column sums of the max-tile are the row sums for block-row bj (symmetry)
        Cs[ty][tx] = cacc;
        __syncthreads();
        if (ty == 0) {
            float t = 0.0f;
            #pragma unroll
            for (int y = 0; y < 8; y++) t += Cs[y][tx];
            atomicAdd(&g_rowsum[c0 + tx], t);
        }
    }
}

__global__ void dinv_kernel() {
    int i = blockIdx.x * blockDim.x + threadIdx.x;
    if (i < N) {
        float rs = g_rowsum[i];
        g_dinv[i] = (rs > 0.0f) ? rsqrtf(rs) : 0.0f;
    }
}

// Pass 2: out[i,j] = d[i]*d[j]*(max(adj[i,j],adj[j,i]) + (i==j)).
// Same tile-pair walk; writes tile (bi,bj) and its transpose (bj,bi).
__global__ __launch_bounds__(256) void pass2_kernel(const float* __restrict__ adj,
                                                    float* __restrict__ out) {
    int bi, bj;
    decode_pair(blockIdx.x, bi, bj);
    const int r0 = bi * T;
    const int c0 = bj * T;
    const int tx = threadIdx.x;
    const int ty = threadIdx.y;

    __shared__ float Bs[T][T + 1];
    __shared__ float Ms[T][T + 1];

    #pragma unroll
    for (int k = 0; k < 4; k++) {
        int ry = ty + k * 8;
        Bs[ry][tx] = adj[(size_t)(c0 + ry) * N + (r0 + tx)];
    }
    __syncthreads();

    const float dj = g_dinv[c0 + tx];
    #pragma unroll
    for (int k = 0; k < 4; k++) {
        int r = ty + k * 8;
        float a = adj[(size_t)(r0 + r) * N + (c0 + tx)];
        float m = fmaxf(a, Bs[tx][r]);
        if (bi == bj && r == tx) m += 1.0f;
        float v = g_dinv[r0 + r] * dj * m;           // broadcast load per warp
        out[(size_t)(r0 + r) * N + (c0 + tx)] = v;
        Ms[r][tx] = v;
    }

    if (bi != bj) {
        __syncthreads();
        #pragma unroll
        for (int k = 0; k < 4; k++) {
            int ry = ty + k * 8;
            out[(size_t)(c0 + ry) * N + (r0 + tx)] = Ms[tx][ry];
        }
    }
}

extern "C" void kernel_launch(void* const* d_in, const int* in_sizes, int n_in,
                              void* d_out, int out_size) {
    const float* adj = (const float*)d_in[0];
    float* out = (float*)d_out;

    zero_rowsum_kernel<<<(N + 255) / 256, 256>>>();
    dim3 blk(32, 8);
    pass1_kernel<<<NPAIRS, blk>>>(adj);
    dinv_kernel<<<(N + 255) / 256, 256>>>();
    pass2_kernel<<<NPAIRS, blk>>>(adj, out);
}

// round 2
// speedup vs baseline: 1.8550x; 1.8550x over previous
#include <cuda_runtime.h>
#include <math.h>

#define N 8192
#define N4 (N / 4)              // row pitch in float4
#define T 32
#define NB (N / T)              // 256 tile-blocks per dim
#define NPAIRS (NB * (NB + 1) / 2)

__device__ float g_rowsum[N];
__device__ float g_dinv[N];

__device__ __forceinline__ int pair_offset(int bi) {
    return bi * NB - (bi * (bi - 1)) / 2;
}

__device__ __forceinline__ void decode_pair(int p, int& bi, int& bj) {
    float disc = (float)((2 * NB + 1) * (2 * NB + 1) - 8 * p);
    int b = (int)(((float)(2 * NB + 1) - sqrtf(disc)) * 0.5f);
    if (b < 0) b = 0;
    if (b > NB - 1) b = NB - 1;
    while (b + 1 <= NB - 1 && pair_offset(b + 1) <= p) b++;
    while (b > 0 && pair_offset(b) > p) b--;
    bi = b;
    bj = bi + (p - pair_offset(b));
}

__global__ void zero_rowsum_kernel() {
    int i = blockIdx.x * blockDim.x + threadIdx.x;
    if (i < N) g_rowsum[i] = 0.0f;
}

// Pass 1: rowsum[i] = sum_j ( max(adj[i,j], adj[j,i]) ) + 1 (self loop)
// One block per upper-triangular 32x32 tile pair. float4 everywhere.
__global__ __launch_bounds__(256) void pass1_kernel(const float4* __restrict__ adj4) {
    int bi, bj;
    decode_pair(blockIdx.x, bi, bj);
    const int r0 = bi * T;
    const int c0 = bj * T;

    const int t    = threadIdx.x;
    const int row  = t >> 3;          // 0..31 tile row
    const int q    = t & 7;           // 0..7 float4 column
    const int lane = t & 31;
    const int wid  = t >> 5;

    __shared__ float  Bs[T][T + 1];
    __shared__ float4 Cs[8][8];       // [warp][q] column partial sums

    // Load A tile row chunk and B (transpose-partner) tile row chunk.
    float4 a = adj4[(size_t)(r0 + row) * N4 + (c0 >> 2) + q];
    float4 b = adj4[(size_t)(c0 + row) * N4 + (r0 >> 2) + q];

    // Stage B in smem (conflict-free: (33*row + 4q+d) % 32 = row+4q+d unique per warp)
    Bs[row][4 * q + 0] = b.x;
    Bs[row][4 * q + 1] = b.y;
    Bs[row][4 * q + 2] = b.z;
    Bs[row][4 * q + 3] = b.w;
    __syncthreads();

    // M[row][c] = max(A[row][c], B[c][row]); gather transposed B (conflict-free)
    float4 m;
    m.x = fmaxf(a.x, Bs[4 * q + 0][row]);
    m.y = fmaxf(a.y, Bs[4 * q + 1][row]);
    m.z = fmaxf(a.z, Bs[4 * q + 2][row]);
    m.w = fmaxf(a.w, Bs[4 * q + 3][row]);

    if (bi == bj) {  // self-loop on the diagonal
        if (4 * q + 0 == row) m.x += 1.0f;
        if (4 * q + 1 == row) m.y += 1.0f;
        if (4 * q + 2 == row) m.z += 1.0f;
        if (4 * q + 3 == row) m.w += 1.0f;
    }

    // --- Row sums: reduce across the 8 lanes sharing a row ---
    float rs = (m.x + m.y) + (m.z + m.w);
    rs += __shfl_down_sync(0xffffffffu, rs, 4, 8);
    rs += __shfl_down_sync(0xffffffffu, rs, 2, 8);
    rs += __shfl_down_sync(0xffffffffu, rs, 1, 8);
    if (q == 0) atomicAdd(&g_rowsum[r0 + row], rs);

    // --- Column sums (= row sums for block bj, by symmetry) ---
    if (bi != bj) {
        float4 c = m;
        c.x += __shfl_xor_sync(0xffffffffu, c.x, 8);
        c.y += __shfl_xor_sync(0xffffffffu, c.y, 8);
        c.z += __shfl_xor_sync(0xffffffffu, c.z, 8);
        c.w += __shfl_xor_sync(0xffffffffu, c.w, 8);
        c.x += __shfl_xor_sync(0xffffffffu, c.x, 16);
        c.y += __shfl_xor_sync(0xffffffffu, c.y, 16);
        c.z += __shfl_xor_sync(0xffffffffu, c.z, 16);
        c.w += __shfl_xor_sync(0xffffffffu, c.w, 16);
        if (lane < 8) Cs[wid][q] = c;   // lane==q here
        __syncthreads();
        if (t < 32) {
            const float* Csf = &Cs[0][0].x;
            float s = 0.0f;
            #pragma unroll
            for (int w = 0; w < 8; w++) s += Csf[w * 32 + t];
            atomicAdd(&g_rowsum[c0 + t], s);
        }
    }
}

__global__ void dinv_kernel() {
    int i = blockIdx.x * blockDim.x + threadIdx.x;
    if (i < N) {
        float rs = g_rowsum[i];
        g_dinv[i] = (rs > 0.0f) ? rsqrtf(rs) : 0.0f;
    }
}

// Pass 2: out[i,j] = d[i]*d[j]*(max(adj[i,j],adj[j,i]) + (i==j)).
// Writes tile (bi,bj) and its transpose (bj,bi), all float4.
__global__ __launch_bounds__(256) void pass2_kernel(const float4* __restrict__ adj4,
                                                    float4* __restrict__ out4) {
    int bi, bj;
    decode_pair(blockIdx.x, bi, bj);
    const int r0 = bi * T;
    const int c0 = bj * T;

    const int t   = threadIdx.x;
    const int row = t >> 3;
    const int q   = t & 7;

    __shared__ float Bs[T][T + 1];
    __shared__ float Ms[T][T + 1];

    float4 a = adj4[(size_t)(r0 + row) * N4 + (c0 >> 2) + q];
    float4 b = adj4[(size_t)(c0 + row) * N4 + (r0 >> 2) + q];

    Bs[row][4 * q + 0] = b.x;
    Bs[row][4 * q + 1] = b.y;
    Bs[row][4 * q + 2] = b.z;
    Bs[row][4 * q + 3] = b.w;
    __syncthreads();

    float4 m;
    m.x = fmaxf(a.x, Bs[4 * q + 0][row]);
    m.y = fmaxf(a.y, Bs[4 * q + 1][row]);
    m.z = fmaxf(a.z, Bs[4 * q + 2][row]);
    m.w = fmaxf(a.w, Bs[4 * q + 3][row]);

    if (bi == bj) {
        if (4 * q + 0 == row) m.x += 1.0f;
        if (4 * q + 1 == row) m.y += 1.0f;
        if (4 * q + 2 == row) m.z += 1.0f;
        if (4 * q + 3 == row) m.w += 1.0f;
    }

    const float  di  = g_dinv[r0 + row];
    const float4 dj4 = ((const float4*)g_dinv)[(c0 >> 2) + q];

    float4 v;
    v.x = di * dj4.x * m.x;
    v.y = di * dj4.y * m.y;
    v.z = di * dj4.z * m.z;
    v.w = di * dj4.w * m.w;

    out4[(size_t)(r0 + row) * N4 + (c0 >> 2) + q] = v;

    if (bi != bj) {
        Ms[row][4 * q + 0] = v.x;
        Ms[row][4 * q + 1] = v.y;
        Ms[row][4 * q + 2] = v.z;
        Ms[row][4 * q + 3] = v.w;
        __syncthreads();

        float4 tr;
        tr.x = Ms[4 * q + 0][row];
        tr.y = Ms[4 * q + 1][row];
        tr.z = Ms[4 * q + 2][row];
        tr.w = Ms[4 * q + 3][row];
        out4[(size_t)(c0 + row) * N4 + (r0 >> 2) + q] = tr;
    }
}

extern "C" void kernel_launch(void* const* d_in, const int* in_sizes, int n_in,
                              void* d_out, int out_size) {
    const float4* adj4 = (const float4*)d_in[0];
    float4* out4 = (float4*)d_out;

    zero_rowsum_kernel<<<(N + 255) / 256, 256>>>();
    pass1_kernel<<<NPAIRS, 256>>>(adj4);
    dinv_kernel<<<(N + 255) / 256, 256>>>();
    pass2_kernel<<<NPAIRS, 256>>>(adj4, out4);
}

// round 3
// speedup vs baseline: 1.9593x; 1.0562x over previous
#include <cuda_runtime.h>
#include <math.h>

#define N 8192
#define N4 (N / 4)              // row pitch in float4
#define T 64
#define NB (N / T)              // 128 tile-blocks per dim
#define NPAIRS (NB * (NB + 1) / 2)   // 8256

__device__ float g_rowsum[N];
__device__ float g_dinv[N];

__device__ __forceinline__ int pair_offset(int bi) {
    return bi * NB - (bi * (bi - 1)) / 2;
}

__device__ __forceinline__ void decode_pair(int p, int& bi, int& bj) {
    float disc = (float)((2 * NB + 1) * (2 * NB + 1) - 8 * p);
    int b = (int)(((float)(2 * NB + 1) - sqrtf(disc)) * 0.5f);
    if (b < 0) b = 0;
    if (b > NB - 1) b = NB - 1;
    while (b + 1 <= NB - 1 && pair_offset(b + 1) <= p) b++;
    while (b > 0 && pair_offset(b) > p) b--;
    bi = b;
    bj = bi + (p - pair_offset(b));
}

__global__ void init_rowsum_kernel() {
    int i = blockIdx.x * blockDim.x + threadIdx.x;
    if (i < N) g_rowsum[i] = 1.0f;   // self-loop pre-added
}

// Pass 1: rowsum[i] += sum_j max(adj[i,j], adj[j,i]).
// One block per upper-triangular 64x64 tile pair; 8 LDG.128 per thread up front.
__global__ __launch_bounds__(256) void pass1_kernel(const float4* __restrict__ adj4) {
    int bi, bj;
    decode_pair(blockIdx.x, bi, bj);
    const int r0 = bi * T;
    const int c0 = bj * T;

    const int t    = threadIdx.x;
    const int q    = t & 15;     // float4 column 0..15
    const int rr   = t >> 4;     // row group 0..15
    const int lane = t & 31;
    const int wid  = t >> 5;

    __shared__ float Bs[T][T + 1];
    __shared__ float Cs[8][T];

    float4 a[4], b[4];
    #pragma unroll
    for (int k = 0; k < 4; k++) {
        int row = rr + 16 * k;
        a[k] = adj4[(size_t)(r0 + row) * N4 + (c0 >> 2) + q];
        b[k] = adj4[(size_t)(c0 + row) * N4 + (r0 >> 2) + q];
    }
    #pragma unroll
    for (int k = 0; k < 4; k++) {
        int row = rr + 16 * k;
        Bs[row][4 * q + 0] = b[k].x;
        Bs[row][4 * q + 1] = b[k].y;
        Bs[row][4 * q + 2] = b[k].z;
        Bs[row][4 * q + 3] = b[k].w;
    }
    __syncthreads();

    float cx = 0.0f, cy = 0.0f, cz = 0.0f, cw = 0.0f;
    #pragma unroll
    for (int k = 0; k < 4; k++) {
        int row = rr + 16 * k;
        float4 m;
        m.x = fmaxf(a[k].x, Bs[4 * q + 0][row]);
        m.y = fmaxf(a[k].y, Bs[4 * q + 1][row]);
        m.z = fmaxf(a[k].z, Bs[4 * q + 2][row]);
        m.w = fmaxf(a[k].w, Bs[4 * q + 3][row]);

        // row sum over the 16 lanes sharing this row (lanes 0-15 / 16-31)
        float rs = (m.x + m.y) + (m.z + m.w);
        rs += __shfl_down_sync(0xffffffffu, rs, 8, 16);
        rs += __shfl_down_sync(0xffffffffu, rs, 4, 16);
        rs += __shfl_down_sync(0xffffffffu, rs, 2, 16);
        rs += __shfl_down_sync(0xffffffffu, rs, 1, 16);
        if (q == 0) atomicAdd(&g_rowsum[r0 + row], rs);

        cx += m.x; cy += m.y; cz += m.z; cw += m.w;
    }

    if (bi != bj) {
        // column sums == row sums for block-row bj (symmetry of the max)
        cx += __shfl_xor_sync(0xffffffffu, cx, 16);
        cy += __shfl_xor_sync(0xffffffffu, cy, 16);
        cz += __shfl_xor_sync(0xffffffffu, cz, 16);
        cw += __shfl_xor_sync(0xffffffffu, cw, 16);
        if (lane < 16) {
            Cs[wid][4 * q + 0] = cx;
            Cs[wid][4 * q + 1] = cy;
            Cs[wid][4 * q + 2] = cz;
            Cs[wid][4 * q + 3] = cw;
        }
        __syncthreads();
        if (t < T) {
            float s = 0.0f;
            #pragma unroll
            for (int w = 0; w < 8; w++) s += Cs[w][t];
            atomicAdd(&g_rowsum[c0 + t], s);
        }
    }
}

__global__ void dinv_kernel() {
    int i = blockIdx.x * blockDim.x + threadIdx.x;
    if (i < N) {
        float rs = g_rowsum[i];
        g_dinv[i] = (rs > 0.0f) ? rsqrtf(rs) : 0.0f;
    }
}

// Pass 2: out[i,j] = d[i]*d[j]*(max(adj[i,j],adj[j,i]) + (i==j)).
// Reverse pair order so early reads hit L2 lines left warm by pass1's tail.
__global__ __launch_bounds__(256) void pass2_kernel(const float4* __restrict__ adj4,
                                                    float4* __restrict__ out4) {
    int bi, bj;
    decode_pair(NPAIRS - 1 - (int)blockIdx.x, bi, bj);
    const int r0 = bi * T;
    const int c0 = bj * T;

    const int t  = threadIdx.x;
    const int q  = t & 15;
    const int rr = t >> 4;

    __shared__ float Bs[T][T + 1];
    __shared__ float Ms[T][T + 1];

    float4 a[4], b[4];
    #pragma unroll
    for (int k = 0; k < 4; k++) {
        int row = rr + 16 * k;
        a[k] = adj4[(size_t)(r0 + row) * N4 + (c0 >> 2) + q];
        b[k] = adj4[(size_t)(c0 + row) * N4 + (r0 >> 2) + q];
    }
    #pragma unroll
    for (int k = 0; k < 4; k++) {
        int row = rr + 16 * k;
        Bs[row][4 * q + 0] = b[k].x;
        Bs[row][4 * q + 1] = b[k].y;
        Bs[row][4 * q + 2] = b[k].z;
        Bs[row][4 * q + 3] = b[k].w;
    }
    __syncthreads();

    const float4 dj4 = ((const float4*)g_dinv)[(c0 >> 2) + q];
    const bool diag = (bi == bj);

    #pragma unroll
    for (int k = 0; k < 4; k++) {
        int row = rr + 16 * k;
        float4 m;
        m.x = fmaxf(a[k].x, Bs[4 * q + 0][row]);
        m.y = fmaxf(a[k].y, Bs[4 * q + 1][row]);
        m.z = fmaxf(a[k].z, Bs[4 * q + 2][row]);
        m.w = fmaxf(a[k].w, Bs[4 * q + 3][row]);
        if (diag) {
            if (4 * q + 0 == row) m.x += 1.0f;
            if (4 * q + 1 == row) m.y += 1.0f;
            if (4 * q + 2 == row) m.z += 1.0f;
            if (4 * q + 3 == row) m.w += 1.0f;
        }
        const float di = g_dinv[r0 + row];
        float4 v;
        v.x = di * dj4.x * m.x;
        v.y = di * dj4.y * m.y;
        v.z = di * dj4.z * m.z;
        v.w = di * dj4.w * m.w;
        out4[(size_t)(r0 + row) * N4 + (c0 >> 2) + q] = v;
        if (!diag) {
            Ms[row][4 * q + 0] = v.x;
            Ms[row][4 * q + 1] = v.y;
            Ms[row][4 * q + 2] = v.z;
            Ms[row][4 * q + 3] = v.w;
        }
    }

    if (!diag) {
        __syncthreads();
        #pragma unroll
        for (int k = 0; k < 4; k++) {
            int row = rr + 16 * k;
            float4 tr;
            tr.x = Ms[4 * q + 0][row];
            tr.y = Ms[4 * q + 1][row];
            tr.z = Ms[4 * q + 2][row];
            tr.w = Ms[4 * q + 3][row];
            out4[(size_t)(c0 + row) * N4 + (r0 >> 2) + q] = tr;
        }
    }
}

extern "C" void kernel_launch(void* const* d_in, const int* in_sizes, int n_in,
                              void* d_out, int out_size) {
    const float4* adj4 = (const float4*)d_in[0];
    float4* out4 = (float4*)d_out;

    init_rowsum_kernel<<<(N + 255) / 256, 256>>>();
    pass1_kernel<<<NPAIRS, 256>>>(adj4);
    dinv_kernel<<<(N + 255) / 256, 256>>>();
    pass2_kernel<<<NPAIRS, 256>>>(adj4, out4);
}